// round 1
// baseline (speedup 1.0000x reference)
#include <cuda_runtime.h>

// Problem constants: x is [B=8, H=512, W=512, C=32] float32, NHWC.
// out[b,h,w,c] = ( x + sum over 7 nested block-means (8..512) ) / 8.
// softmax(a) over a size-1 axis == 1.0, so input a is mathematically dead.

#define NB 8
#define HH 512
#define WW 512
#define C4 8          // float4 groups per pixel (32 channels)

// Scratch (device globals — allocation-free per harness rules)
__device__ float4 g_p8[NB * 64 * 64 * C4];   // 8x8-block means, [b][64][64][c4], 4 MB
__device__ float4 g_cs[NB * 64 * 64 * C4];   // precombined (sum of 7 level means)/8, 4 MB

__device__ __forceinline__ float4 f4add(float4 a, float4 b) {
    return make_float4(a.x + b.x, a.y + b.y, a.z + b.z, a.w + b.w);
}
__device__ __forceinline__ float4 f4scale(float4 a, float s) {
    return make_float4(a.x * s, a.y * s, a.z * s, a.w * s);
}

// ---------------------------------------------------------------------------
// Kernel A: 8x8 average pool. One warp per (b, cell). Reads all of x once.
// Lane layout: c4 = lane&7 (channel float4 group), p = lane>>3 (pixel sub-id).
// Each warp iteration loads 4 consecutive pixels x 128B = 512B contiguous.
// ---------------------------------------------------------------------------
__global__ void __launch_bounds__(256) pool8_kernel(const float4* __restrict__ x) {
    int warp = (blockIdx.x * 256 + threadIdx.x) >> 5;   // 0 .. 32767
    int lane = threadIdx.x & 31;
    int b    = warp >> 12;          // 4096 cells per batch
    int cell = warp & 4095;         // (bi<<6)|bj
    int bi   = cell >> 6;
    int bj   = cell & 63;
    int c4   = lane & 7;
    int p    = lane >> 3;

    int rowbase = b * HH + bi * 8;
    int colbase = bj * 8;

    float4 s = make_float4(0.f, 0.f, 0.f, 0.f);
    #pragma unroll
    for (int k = 0; k < 16; ++k) {
        int pix = k * 4 + p;              // 0..63
        int i = pix >> 3;
        int j = pix & 7;
        float4 v = x[((rowbase + i) * WW + colbase + j) * C4 + c4];
        s.x += v.x; s.y += v.y; s.z += v.z; s.w += v.w;
    }
    // reduce across the 4 p-lanes holding the same channel group
    #pragma unroll
    for (int m = 8; m <= 16; m <<= 1) {
        s.x += __shfl_xor_sync(0xffffffffu, s.x, m);
        s.y += __shfl_xor_sync(0xffffffffu, s.y, m);
        s.z += __shfl_xor_sync(0xffffffffu, s.z, m);
        s.w += __shfl_xor_sync(0xffffffffu, s.w, m);
    }
    if (p == 0) {
        g_p8[(b * 4096 + cell) * C4 + c4] = f4scale(s, 1.0f / 64.0f);
    }
}

// ---------------------------------------------------------------------------
// Kernel B: hierarchical combine. One block per (b, channel-group g).
// Builds means for windows 16..512 from P8 in shared memory, then writes
// Cs[cell] = (m8 + m16 + m32 + m64 + m128 + m256 + m512) / 8.
// Tiny (4 MB in / 4 MB out, L2-resident).
// ---------------------------------------------------------------------------
__global__ void __launch_bounds__(1024) combine_kernel() {
    __shared__ float4 s16[1024];   // 32x32
    __shared__ float4 s32[256];    // 16x16
    __shared__ float4 s64[64];     // 8x8
    __shared__ float4 s128[16];    // 4x4
    __shared__ float4 s256[4];     // 2x2
    __shared__ float4 s512[1];     // 1x1

    int b = blockIdx.x >> 3;
    int g = blockIdx.x & 7;
    int t = threadIdx.x;
    int gi = t >> 5;               // 0..31
    int gj = t & 31;

    // Each thread owns the 2x2 group of P8 cells at (2gi.., 2gj..)
    float4 p[4];
    #pragma unroll
    for (int di = 0; di < 2; ++di)
        #pragma unroll
        for (int dj = 0; dj < 2; ++dj)
            p[di * 2 + dj] =
                g_p8[((b * 64 + 2 * gi + di) * 64 + 2 * gj + dj) * C4 + g];

    float4 m16 = f4scale(f4add(f4add(p[0], p[1]), f4add(p[2], p[3])), 0.25f);
    s16[gi * 32 + gj] = m16;
    __syncthreads();

    if (t < 256) {
        int i = t >> 4, j = t & 15;
        float4 a = f4add(f4add(s16[(2*i) * 32 + 2*j], s16[(2*i) * 32 + 2*j + 1]),
                         f4add(s16[(2*i+1) * 32 + 2*j], s16[(2*i+1) * 32 + 2*j + 1]));
        s32[i * 16 + j] = f4scale(a, 0.25f);
    }
    __syncthreads();
    if (t < 64) {
        int i = t >> 3, j = t & 7;
        float4 a = f4add(f4add(s32[(2*i) * 16 + 2*j], s32[(2*i) * 16 + 2*j + 1]),
                         f4add(s32[(2*i+1) * 16 + 2*j], s32[(2*i+1) * 16 + 2*j + 1]));
        s64[i * 8 + j] = f4scale(a, 0.25f);
    }
    __syncthreads();
    if (t < 16) {
        int i = t >> 2, j = t & 3;
        float4 a = f4add(f4add(s64[(2*i) * 8 + 2*j], s64[(2*i) * 8 + 2*j + 1]),
                         f4add(s64[(2*i+1) * 8 + 2*j], s64[(2*i+1) * 8 + 2*j + 1]));
        s128[i * 4 + j] = f4scale(a, 0.25f);
    }
    __syncthreads();
    if (t < 4) {
        int i = t >> 1, j = t & 1;
        float4 a = f4add(f4add(s128[(2*i) * 4 + 2*j], s128[(2*i) * 4 + 2*j + 1]),
                         f4add(s128[(2*i+1) * 4 + 2*j], s128[(2*i+1) * 4 + 2*j + 1]));
        s256[i * 2 + j] = f4scale(a, 0.25f);
    }
    __syncthreads();
    if (t == 0) {
        float4 a = f4add(f4add(s256[0], s256[1]), f4add(s256[2], s256[3]));
        s512[0] = f4scale(a, 0.25f);
    }
    __syncthreads();

    float4 base = s16[gi * 32 + gj];
    base = f4add(base, s32[(gi >> 1) * 16 + (gj >> 1)]);
    base = f4add(base, s64[(gi >> 2) * 8 + (gj >> 2)]);
    base = f4add(base, s128[(gi >> 3) * 4 + (gj >> 3)]);
    base = f4add(base, s256[(gi >> 4) * 2 + (gj >> 4)]);
    base = f4add(base, s512[0]);

    #pragma unroll
    for (int di = 0; di < 2; ++di)
        #pragma unroll
        for (int dj = 0; dj < 2; ++dj) {
            float4 comb = f4scale(f4add(p[di * 2 + dj], base), 0.125f);
            g_cs[((b * 64 + 2 * gi + di) * 64 + 2 * gj + dj) * C4 + g] = comb;
        }
}

// ---------------------------------------------------------------------------
// Kernel C: out = x * 0.125 + Cs[cell]. Streams x once, Cs is L2/L1-hot
// (each 128B cell line serves 64 pixels).
// ---------------------------------------------------------------------------
__global__ void __launch_bounds__(256) final_kernel(const float4* __restrict__ x,
                                                    float4* __restrict__ out) {
    int idx = blockIdx.x * 256 + threadIdx.x;   // 0 .. 16777215
    int c4  = idx & 7;
    int pix = idx >> 3;
    int col = pix & 511;
    int row = (pix >> 9) & 511;
    int b   = pix >> 18;

    float4 v = x[idx];
    float4 c = __ldg(&g_cs[((b * 64 + (row >> 3)) * 64 + (col >> 3)) * C4 + c4]);
    out[idx] = make_float4(v.x * 0.125f + c.x,
                           v.y * 0.125f + c.y,
                           v.z * 0.125f + c.z,
                           v.w * 0.125f + c.w);
}

extern "C" void kernel_launch(void* const* d_in, const int* in_sizes, int n_in,
                              void* d_out, int out_size) {
    const float4* x = (const float4*)d_in[0];   // d_in[1] (a) is mathematically dead
    float4* out = (float4*)d_out;
    (void)in_sizes; (void)n_in; (void)out_size;

    pool8_kernel<<<4096, 256>>>(x);        // 32768 warps, one per 8x8 cell
    combine_kernel<<<64, 1024>>>();        // one block per (batch, channel-group)
    final_kernel<<<65536, 256>>>(x, out);  // 16M float4
}